// round 12
// baseline (speedup 1.0000x reference)
#include <cuda_runtime.h>
#include <cuda.h>
#include <cuda_fp16.h>
#include <cstdint>
#include <cstddef>
#include <cstring>

// ---------------------------------------------------------------------------
// Problem constants
// ---------------------------------------------------------------------------
#define M_TOT 8192        // B*S
#define N_TOT 4096        // D_OUT
#define K_TOT 4096        // D_IN
#define RANK  16
#define K2    4096
#define NCHUNK 64         // K2 / 64 per tile
#define STAGES 3
#define GEMM_THREADS 256
#define NTILES 2048       // (M/128)*(N/128)
#define PERSIST 296       // 2 CTAs/SM * 148 SMs

// smem layout (bytes, relative to dynamic smem base; base is 1024-aligned)
#define OFF_FULL   0      // 3 x 8B
#define OFF_EMPTY  32     // 3 x 8B
#define OFF_TILES  1024
#define TILE_BYTES 16384  // 128 rows x 128B (64 fp16)
#define SMEM_TOTAL (OFF_TILES + 2 * STAGES * TILE_BYTES)   // 99328

// prep_w tiling
#define PW_TK 128
#define PW_TN 32

// ---------------------------------------------------------------------------
// Device scratch (allocation-free rule: __device__ globals)
// ---------------------------------------------------------------------------
__device__ __half g_xh[(size_t)M_TOT * K2];   // [8192, 4096] fp16  64 MB
__device__ __half g_wb[(size_t)N_TOT * K2];   // [4096, 4096] fp16  32 MB

// ---------------------------------------------------------------------------
// PTX helpers
// ---------------------------------------------------------------------------
__device__ __forceinline__ uint32_t smem_u32(const void* p) {
    uint32_t a;
    asm("{ .reg .u64 t; cvta.to.shared.u64 t, %1; cvt.u32.u64 %0, t; }"
        : "=r"(a) : "l"(p));
    return a;
}
__device__ __forceinline__ void mbar_init(uint32_t a, uint32_t n) {
    asm volatile("mbarrier.init.shared.b64 [%0], %1;" :: "r"(a), "r"(n) : "memory");
}
__device__ __forceinline__ void mbar_expect_tx(uint32_t a, uint32_t bytes) {
    asm volatile("mbarrier.arrive.expect_tx.shared.b64 _, [%0], %1;"
                 :: "r"(a), "r"(bytes) : "memory");
}
__device__ __forceinline__ void mbar_arrive(uint32_t a) {
    asm volatile("mbarrier.arrive.shared.b64 _, [%0];" :: "r"(a) : "memory");
}
__device__ __forceinline__ void mbar_wait(uint32_t a, uint32_t parity) {
    asm volatile(
        "{\n\t.reg .pred P;\n"
        "W_%=:\n\t"
        "mbarrier.try_wait.parity.acquire.cta.shared::cta.b64 P, [%0], %1, 0x989680;\n\t"
        "@P bra D_%=;\n\t"
        "bra W_%=;\n"
        "D_%=:\n\t}"
        :: "r"(a), "r"(parity) : "memory");
}
__device__ __forceinline__ void tma_2d(uint32_t dst, const CUtensorMap* tm,
                                       int cx, int cy, uint32_t mbar) {
    asm volatile(
        "cp.async.bulk.tensor.2d.shared::cta.global.tile.mbarrier::complete_tx::bytes "
        "[%0], [%1, {%2, %3}], [%4];"
        :: "r"(dst), "l"(tm), "r"(cx), "r"(cy), "r"(mbar) : "memory");
}
__device__ __forceinline__ void ldsm4(uint32_t& r0, uint32_t& r1, uint32_t& r2,
                                      uint32_t& r3, uint32_t addr) {
    asm volatile("ldmatrix.sync.aligned.m8n8.x4.shared.b16 {%0,%1,%2,%3}, [%4];"
                 : "=r"(r0), "=r"(r1), "=r"(r2), "=r"(r3) : "r"(addr));
}
__device__ __forceinline__ void mma16816(float& d0, float& d1, float& d2, float& d3,
                                         uint32_t a0, uint32_t a1, uint32_t a2, uint32_t a3,
                                         uint32_t b0, uint32_t b1) {
    asm volatile(
        "mma.sync.aligned.m16n8k16.row.col.f32.f16.f16.f32 "
        "{%0,%1,%2,%3}, {%4,%5,%6,%7}, {%8,%9}, {%0,%1,%2,%3};"
        : "+f"(d0), "+f"(d1), "+f"(d2), "+f"(d3)
        : "r"(a0), "r"(a1), "r"(a2), "r"(a3), "r"(b0), "r"(b1));
}

// ---------------------------------------------------------------------------
// Kernel 1: pure stream convert  g_xh = fp16(x).  8 elements / thread.
// (R10 version: 26.8us @ 78.6% DRAM)
// ---------------------------------------------------------------------------
__global__ void __launch_bounds__(256) conv_x_kernel(const float* __restrict__ x) {
    size_t i = ((size_t)blockIdx.x * 256 + threadIdx.x) * 8;
    float4 v0 = *(const float4*)(x + i);
    float4 v1 = *(const float4*)(x + i + 4);
    __half2 h[4];
    h[0] = __floats2half2_rn(v0.x, v0.y);
    h[1] = __floats2half2_rn(v0.z, v0.w);
    h[2] = __floats2half2_rn(v1.x, v1.y);
    h[3] = __floats2half2_rn(v1.z, v1.w);
    uint4 u;
    memcpy(&u, h, 16);
    *(uint4*)(g_xh + i) = u;
}

// ---------------------------------------------------------------------------
// Kernel 2: W_eff[n][k] = fp16( q[n][k] + (1/scale) * sum_r A[k][r]*B[r][n] )
// (R10 version)
// ---------------------------------------------------------------------------
__global__ void __launch_bounds__(256) prep_w_kernel(const int* __restrict__ q,
                                                     const float* __restrict__ lA,
                                                     const float* __restrict__ lB,
                                                     const float* __restrict__ scales) {
    __shared__ float sA[PW_TK][16];
    __shared__ float sB[16][PW_TN];
    int tid = threadIdx.x;
    int k0 = blockIdx.x * PW_TK, n0 = blockIdx.y * PW_TN;
    float c = 1.0f / __ldg(scales);

    #pragma unroll
    for (int it = 0; it < 2; it++) {
        int idx = tid + it * 256;
        int k = idx >> 2, qd = idx & 3;
        float4 a = ((const float4*)(lA + (size_t)(k0 + k) * RANK))[qd];
        sA[k][qd * 4 + 0] = a.x;
        sA[k][qd * 4 + 1] = a.y;
        sA[k][qd * 4 + 2] = a.z;
        sA[k][qd * 4 + 3] = a.w;
    }
    if (tid < 128) {
        int r = tid >> 3, qd = tid & 7;
        float4 b = ((const float4*)(lB + (size_t)r * N_TOT + n0))[qd];
        sB[r][qd * 4 + 0] = b.x * c;
        sB[r][qd * 4 + 1] = b.y * c;
        sB[r][qd * 4 + 2] = b.z * c;
        sB[r][qd * 4 + 3] = b.w * c;
    }
    __syncthreads();

    int tn = tid & 15, tk = tid >> 4;
    float bb[2][16];
    #pragma unroll
    for (int nn = 0; nn < 2; nn++)
        #pragma unroll
        for (int r = 0; r < 16; r++) bb[nn][r] = sB[r][tn * 2 + nn];

    int qa[2][8];
    #pragma unroll
    for (int nn = 0; nn < 2; nn++) {
        int n = n0 + tn * 2 + nn;
        const int4* qp = (const int4*)(q + (size_t)n * K_TOT + k0 + tk * 8);
        int4 u0 = qp[0], u1 = qp[1];
        qa[nn][0] = u0.x; qa[nn][1] = u0.y; qa[nn][2] = u0.z; qa[nn][3] = u0.w;
        qa[nn][4] = u1.x; qa[nn][5] = u1.y; qa[nn][6] = u1.z; qa[nn][7] = u1.w;
    }

    __half2 owt[2][4];
    float wprev[2];
    #pragma unroll
    for (int kk = 0; kk < 8; kk++) {
        const float4* ap = (const float4*)&sA[tk * 8 + kk][0];
        float4 a0 = ap[0], a1 = ap[1], a2 = ap[2], a3 = ap[3];
        float av[16] = {a0.x, a0.y, a0.z, a0.w, a1.x, a1.y, a1.z, a1.w,
                        a2.x, a2.y, a2.z, a2.w, a3.x, a3.y, a3.z, a3.w};
        #pragma unroll
        for (int nn = 0; nn < 2; nn++) {
            float s0 = 0.f, s1 = 0.f;
            #pragma unroll
            for (int r = 0; r < 16; r += 2) {
                s0 = fmaf(av[r], bb[nn][r], s0);
                s1 = fmaf(av[r + 1], bb[nn][r + 1], s1);
            }
            float w = (float)qa[nn][kk] + (s0 + s1);
            if (kk & 1) owt[nn][kk >> 1] = __floats2half2_rn(wprev[nn], w);
            else        wprev[nn] = w;
        }
    }
    #pragma unroll
    for (int nn = 0; nn < 2; nn++) {
        int n = n0 + tn * 2 + nn;
        uint4 u;
        memcpy(&u, owt[nn], 16);
        *(uint4*)(g_wb + (size_t)n * K2 + k0 + tk * 8) = u;
    }
}

// ---------------------------------------------------------------------------
// Kernel 3: PERSISTENT fp16 mma.sync GEMM.
//   296 CTAs; each walks tiles bid, bid+296, ... with one continuous
//   3-stage TMA pipeline (global chunk counter; stage/parity never reset).
//   Producer prefetches the next tile's chunks during the current epilogue.
// ---------------------------------------------------------------------------
__global__ void __launch_bounds__(GEMM_THREADS, 2) qlora_gemm_kernel(
    const __grid_constant__ CUtensorMap tmA,
    const __grid_constant__ CUtensorMap tmB,
    const float* __restrict__ scales,
    const float* __restrict__ bias,
    float* __restrict__ out)
{
    extern __shared__ __align__(1024) char smem[];
    uint32_t sb = smem_u32(smem);
    const uint32_t FULLB  = sb + OFF_FULL;
    const uint32_t EMPTYB = sb + OFF_EMPTY;
    const uint32_t SA0 = sb + OFF_TILES;
    const uint32_t SB0 = SA0 + STAGES * TILE_BYTES;

    int tid = threadIdx.x, wid = tid >> 5, lane = tid & 31;
    int mwarp = wid >> 2, nwarp = wid & 3;
    int bid = blockIdx.x;

    int ntiles = (NTILES - bid + PERSIST - 1) / PERSIST;   // tiles for this CTA
    int total = ntiles * NCHUNK;                            // total chunks

    if (tid == 0) {
        #pragma unroll
        for (int s = 0; s < STAGES; s++) {
            mbar_init(FULLB + 8 * s, 1);
            mbar_init(EMPTYB + 8 * s, 8);      // one arrive per warp
        }
        asm volatile("fence.proxy.async.shared::cta;" ::: "memory");
    }
    __syncthreads();

    // Prologue: issue global chunks 0..STAGES-2
    if (tid == 0) {
        #pragma unroll
        for (int gq = 0; gq < STAGES - 1; gq++) {
            int t = bid + (gq >> 6) * PERSIST;        // gq<64 so tile 0 of this CTA
            int m0p = (t & 63) * 128, n0p = (t >> 6) * 128;
            mbar_expect_tx(FULLB + 8 * gq, 2 * TILE_BYTES);
            tma_2d(SA0 + gq * TILE_BYTES, &tmA, (gq & 63) * 64, m0p, FULLB + 8 * gq);
            tma_2d(SB0 + gq * TILE_BYTES, &tmB, (gq & 63) * 64, n0p, FULLB + 8 * gq);
        }
    }

    // Per-thread ldmatrix address components (SW128: phys16B = c ^ (row&7))
    uint32_t aRowOff[4], aSw[4];
    {
        int ar = lane & 15;
        #pragma unroll
        for (int i = 0; i < 4; i++) {
            int row = mwarp * 64 + i * 16 + ar;
            aRowOff[i] = row * 128;
            aSw[i] = row & 7;
        }
    }
    uint32_t a_dc = lane >> 4;
    uint32_t bRowOff[2], bSw[2];
    {
        #pragma unroll
        for (int jj = 0; jj < 2; jj++) {
            int row = nwarp * 32 + jj * 16 + ((lane >> 4) << 3) + (lane & 7);
            bRowOff[jj] = row * 128;
            bSw[jj] = row & 7;
        }
    }
    uint32_t b_dc = (lane >> 3) & 1;

    float acc[4][4][4];
    #pragma unroll
    for (int i = 0; i < 4; i++)
        #pragma unroll
        for (int j = 0; j < 4; j++)
            #pragma unroll
            for (int d = 0; d < 4; d++) acc[i][j][d] = 0.f;

    float scl = __ldg(scales);
    int g = lane >> 2, tig = lane & 3;
    int tile = bid;                       // current tile id
    int m0 = (tile & 63) * 128, n0 = (tile >> 6) * 128;

    for (int G = 0; G < total; G++) {
        // producer: issue global chunk G+STAGES-1
        if (tid == 0) {
            int n = G + STAGES - 1;
            if (n < total) {
                int s = n % STAGES, r = n / STAGES;
                int t = bid + (n >> 6) * PERSIST;
                int m0p = (t & 63) * 128, n0p = (t >> 6) * 128;
                mbar_wait(EMPTYB + 8 * s, (r + 1) & 1);   // fresh stages pass (parity 1)
                mbar_expect_tx(FULLB + 8 * s, 2 * TILE_BYTES);
                tma_2d(SA0 + s * TILE_BYTES, &tmA, (n & 63) * 64, m0p, FULLB + 8 * s);
                tma_2d(SB0 + s * TILE_BYTES, &tmB, (n & 63) * 64, n0p, FULLB + 8 * s);
            }
        }
        int s = G % STAGES, r = G / STAGES;
        mbar_wait(FULLB + 8 * s, r & 1);
        uint32_t sA = SA0 + s * TILE_BYTES;
        uint32_t sBw = SB0 + s * TILE_BYTES;

        #pragma unroll
        for (int ks = 0; ks < 4; ks++) {
            uint32_t cc = 2 * ks;
            uint32_t bfr[8];
            ldsm4(bfr[0], bfr[1], bfr[2], bfr[3],
                  sBw + bRowOff[0] + (((cc + b_dc) ^ bSw[0]) << 4));
            ldsm4(bfr[4], bfr[5], bfr[6], bfr[7],
                  sBw + bRowOff[1] + (((cc + b_dc) ^ bSw[1]) << 4));
            #pragma unroll
            for (int i = 0; i < 4; i++) {
                uint32_t a0, a1, a2, a3;
                ldsm4(a0, a1, a2, a3,
                      sA + aRowOff[i] + (((cc + a_dc) ^ aSw[i]) << 4));
                #pragma unroll
                for (int j = 0; j < 4; j++)
                    mma16816(acc[i][j][0], acc[i][j][1], acc[i][j][2], acc[i][j][3],
                             a0, a1, a2, a3, bfr[2 * j], bfr[2 * j + 1]);
            }
        }
        if (lane == 0) mbar_arrive(EMPTYB + 8 * s);

        // tile boundary: epilogue + reset accumulators; producer already
        // prefetching the next tile's chunks into the free stages.
        if ((G & (NCHUNK - 1)) == (NCHUNK - 1)) {
            #pragma unroll
            for (int i = 0; i < 4; i++) {
                int row = m0 + mwarp * 64 + i * 16 + g;
                #pragma unroll
                for (int j = 0; j < 4; j++) {
                    int lcol = n0 + nwarp * 32 + j * 8 + tig * 2;
                    float b0 = __ldg(bias + lcol), b1 = __ldg(bias + lcol + 1);
                    float2 v0, v1;
                    v0.x = acc[i][j][0] * scl + b0;
                    v0.y = acc[i][j][1] * scl + b1;
                    v1.x = acc[i][j][2] * scl + b0;
                    v1.y = acc[i][j][3] * scl + b1;
                    *(float2*)(out + (size_t)row * N_TOT + lcol) = v0;
                    *(float2*)(out + (size_t)(row + 8) * N_TOT + lcol) = v1;
                    acc[i][j][0] = 0.f; acc[i][j][1] = 0.f;
                    acc[i][j][2] = 0.f; acc[i][j][3] = 0.f;
                }
            }
            tile += PERSIST;
            m0 = (tile & 63) * 128;
            n0 = (tile >> 6) * 128;
        }
    }
}

// ---------------------------------------------------------------------------
// Host launch
// ---------------------------------------------------------------------------
typedef CUresult (*PFN_encodeTiled)(
    CUtensorMap*, CUtensorMapDataType, cuuint32_t, void*,
    const cuuint64_t*, const cuuint64_t*, const cuuint32_t*, const cuuint32_t*,
    CUtensorMapInterleave, CUtensorMapSwizzle, CUtensorMapL2promotion,
    CUtensorMapFloatOOBfill);

static PFN_encodeTiled get_encoder() {
    void* fn = nullptr;
    cudaDriverEntryPointQueryResult qres = cudaDriverEntryPointSymbolNotFound;
    if (cudaGetDriverEntryPointByVersion("cuTensorMapEncodeTiled", &fn, 12000,
                                         cudaEnableDefault, &qres) == cudaSuccess &&
        qres == cudaDriverEntryPointSuccess && fn) {
        return (PFN_encodeTiled)fn;
    }
    fn = nullptr;
    qres = cudaDriverEntryPointSymbolNotFound;
    if (cudaGetDriverEntryPoint("cuTensorMapEncodeTiled", &fn,
                                cudaEnableDefault, &qres) == cudaSuccess &&
        qres == cudaDriverEntryPointSuccess && fn) {
        return (PFN_encodeTiled)fn;
    }
    return nullptr;
}

extern "C" void kernel_launch(void* const* d_in, const int* in_sizes, int n_in,
                              void* d_out, int out_size) {
    const float* x      = (const float*)d_in[0];
    const int*   qw     = (const int*)d_in[1];
    const float* scales = (const float*)d_in[2];
    const float* bias   = (const float*)d_in[3];
    const float* lA     = (const float*)d_in[4];
    const float* lB     = (const float*)d_in[5];
    float* out = (float*)d_out;

    void* p_xh = nullptr;
    void* p_wb = nullptr;
    cudaGetSymbolAddress(&p_xh, g_xh);
    cudaGetSymbolAddress(&p_wb, g_wb);

    static PFN_encodeTiled enc = nullptr;
    if (!enc) enc = get_encoder();
    if (!enc || !p_xh || !p_wb) return;

    CUtensorMap tmA, tmB;
    {
        cuuint64_t dims[2]    = {(cuuint64_t)K2, (cuuint64_t)M_TOT};
        cuuint64_t strides[1] = {(cuuint64_t)K2 * 2};
        cuuint32_t box[2]     = {64, 128};
        cuuint32_t es[2]      = {1, 1};
        if (enc(&tmA, CU_TENSOR_MAP_DATA_TYPE_FLOAT16, 2, p_xh, dims, strides, box, es,
                CU_TENSOR_MAP_INTERLEAVE_NONE, CU_TENSOR_MAP_SWIZZLE_128B,
                CU_TENSOR_MAP_L2_PROMOTION_L2_128B,
                CU_TENSOR_MAP_FLOAT_OOB_FILL_NONE) != CUDA_SUCCESS) return;
    }
    {
        cuuint64_t dims[2]    = {(cuuint64_t)K2, (cuuint64_t)N_TOT};
        cuuint64_t strides[1] = {(cuuint64_t)K2 * 2};
        cuuint32_t box[2]     = {64, 128};
        cuuint32_t es[2]      = {1, 1};
        if (enc(&tmB, CU_TENSOR_MAP_DATA_TYPE_FLOAT16, 2, p_wb, dims, strides, box, es,
                CU_TENSOR_MAP_INTERLEAVE_NONE, CU_TENSOR_MAP_SWIZZLE_128B,
                CU_TENSOR_MAP_L2_PROMOTION_L2_128B,
                CU_TENSOR_MAP_FLOAT_OOB_FILL_NONE) != CUDA_SUCCESS) return;
    }

    // 1) x -> fp16 (pure stream)
    conv_x_kernel<<<(unsigned)((size_t)M_TOT * K_TOT / 8 / 256), 256>>>(x);
    // 2) W_eff = q + (1/scale) * (A@B)^T -> fp16
    {
        dim3 g2(K_TOT / PW_TK, N_TOT / PW_TN);
        prep_w_kernel<<<g2, 256>>>(qw, lA, lB, scales);
    }
    // 3) persistent GEMM
    cudaFuncSetAttribute(qlora_gemm_kernel,
                         cudaFuncAttributeMaxDynamicSharedMemorySize, SMEM_TOTAL);
    qlora_gemm_kernel<<<PERSIST, GEMM_THREADS, SMEM_TOTAL>>>(
        tmA, tmB, scales, bias, out);
}

// round 13
// speedup vs baseline: 1.0486x; 1.0486x over previous
#include <cuda_runtime.h>
#include <cuda.h>
#include <cuda_fp16.h>
#include <cstdint>
#include <cstddef>
#include <cstring>

// ---------------------------------------------------------------------------
// Problem constants
// ---------------------------------------------------------------------------
#define M_TOT 8192        // B*S
#define N_TOT 4096        // D_OUT
#define K_TOT 4096        // D_IN
#define RANK  16
#define K2    4096
#define NCHUNK 64         // K2 / 64
#define STAGES 3
#define GEMM_THREADS 256

// smem layout (bytes, relative to dynamic smem base; base is 1024-aligned)
#define OFF_FULL   0      // 3 x 8B
#define OFF_EMPTY  32     // 3 x 8B
#define OFF_BIAS   64     // 128 floats
#define OFF_TILES  1024
#define TILE_BYTES 16384  // 128 rows x 128B (64 fp16)
#define SMEM_TOTAL (OFF_TILES + 2 * STAGES * TILE_BYTES)   // 99328

// prep_w tiling
#define PW_TK 128
#define PW_TN 32

// ---------------------------------------------------------------------------
// Device scratch (allocation-free rule: __device__ globals)
// ---------------------------------------------------------------------------
__device__ __half g_xh[(size_t)M_TOT * K2];   // [8192, 4096] fp16  64 MB
__device__ __half g_wb[(size_t)N_TOT * K2];   // [4096, 4096] fp16  32 MB

// ---------------------------------------------------------------------------
// PTX helpers
// ---------------------------------------------------------------------------
__device__ __forceinline__ uint32_t smem_u32(const void* p) {
    uint32_t a;
    asm("{ .reg .u64 t; cvta.to.shared.u64 t, %1; cvt.u32.u64 %0, t; }"
        : "=r"(a) : "l"(p));
    return a;
}
__device__ __forceinline__ void mbar_init(uint32_t a, uint32_t n) {
    asm volatile("mbarrier.init.shared.b64 [%0], %1;" :: "r"(a), "r"(n) : "memory");
}
__device__ __forceinline__ void mbar_expect_tx(uint32_t a, uint32_t bytes) {
    asm volatile("mbarrier.arrive.expect_tx.shared.b64 _, [%0], %1;"
                 :: "r"(a), "r"(bytes) : "memory");
}
__device__ __forceinline__ void mbar_arrive(uint32_t a) {
    asm volatile("mbarrier.arrive.shared.b64 _, [%0];" :: "r"(a) : "memory");
}
__device__ __forceinline__ void mbar_wait(uint32_t a, uint32_t parity) {
    asm volatile(
        "{\n\t.reg .pred P;\n"
        "W_%=:\n\t"
        "mbarrier.try_wait.parity.acquire.cta.shared::cta.b64 P, [%0], %1, 0x989680;\n\t"
        "@P bra D_%=;\n\t"
        "bra W_%=;\n"
        "D_%=:\n\t}"
        :: "r"(a), "r"(parity) : "memory");
}
__device__ __forceinline__ void tma_2d(uint32_t dst, const CUtensorMap* tm,
                                       int cx, int cy, uint32_t mbar) {
    asm volatile(
        "cp.async.bulk.tensor.2d.shared::cta.global.tile.mbarrier::complete_tx::bytes "
        "[%0], [%1, {%2, %3}], [%4];"
        :: "r"(dst), "l"(tm), "r"(cx), "r"(cy), "r"(mbar) : "memory");
}
__device__ __forceinline__ void ldsm4(uint32_t& r0, uint32_t& r1, uint32_t& r2,
                                      uint32_t& r3, uint32_t addr) {
    asm volatile("ldmatrix.sync.aligned.m8n8.x4.shared.b16 {%0,%1,%2,%3}, [%4];"
                 : "=r"(r0), "=r"(r1), "=r"(r2), "=r"(r3) : "r"(addr));
}
__device__ __forceinline__ void mma16816(float& d0, float& d1, float& d2, float& d3,
                                         uint32_t a0, uint32_t a1, uint32_t a2, uint32_t a3,
                                         uint32_t b0, uint32_t b1) {
    asm volatile(
        "mma.sync.aligned.m16n8k16.row.col.f32.f16.f16.f32 "
        "{%0,%1,%2,%3}, {%4,%5,%6,%7}, {%8,%9}, {%0,%1,%2,%3};"
        : "+f"(d0), "+f"(d1), "+f"(d2), "+f"(d3)
        : "r"(a0), "r"(a1), "r"(a2), "r"(a3), "r"(b0), "r"(b1));
}

// ---------------------------------------------------------------------------
// Kernel 1: pure stream convert  g_xh = fp16(x).  8 elements / thread.
// (R10 version: 26.8us @ 78.6% DRAM — at HBM floor)
// ---------------------------------------------------------------------------
__global__ void __launch_bounds__(256) conv_x_kernel(const float* __restrict__ x) {
    size_t i = ((size_t)blockIdx.x * 256 + threadIdx.x) * 8;
    float4 v0 = *(const float4*)(x + i);
    float4 v1 = *(const float4*)(x + i + 4);
    __half2 h[4];
    h[0] = __floats2half2_rn(v0.x, v0.y);
    h[1] = __floats2half2_rn(v0.z, v0.w);
    h[2] = __floats2half2_rn(v1.x, v1.y);
    h[3] = __floats2half2_rn(v1.z, v1.w);
    uint4 u;
    memcpy(&u, h, 16);
    *(uint4*)(g_xh + i) = u;
}

// ---------------------------------------------------------------------------
// Kernel 2: W_eff[n][k] = fp16( q[n][k] + (1/scale) * sum_r A[k][r]*B[r][n] )
// (R10 version)
// ---------------------------------------------------------------------------
__global__ void __launch_bounds__(256) prep_w_kernel(const int* __restrict__ q,
                                                     const float* __restrict__ lA,
                                                     const float* __restrict__ lB,
                                                     const float* __restrict__ scales) {
    __shared__ float sA[PW_TK][16];
    __shared__ float sB[16][PW_TN];
    int tid = threadIdx.x;
    int k0 = blockIdx.x * PW_TK, n0 = blockIdx.y * PW_TN;
    float c = 1.0f / __ldg(scales);

    #pragma unroll
    for (int it = 0; it < 2; it++) {
        int idx = tid + it * 256;
        int k = idx >> 2, qd = idx & 3;
        float4 a = ((const float4*)(lA + (size_t)(k0 + k) * RANK))[qd];
        sA[k][qd * 4 + 0] = a.x;
        sA[k][qd * 4 + 1] = a.y;
        sA[k][qd * 4 + 2] = a.z;
        sA[k][qd * 4 + 3] = a.w;
    }
    if (tid < 128) {
        int r = tid >> 3, qd = tid & 7;
        float4 b = ((const float4*)(lB + (size_t)r * N_TOT + n0))[qd];
        sB[r][qd * 4 + 0] = b.x * c;
        sB[r][qd * 4 + 1] = b.y * c;
        sB[r][qd * 4 + 2] = b.z * c;
        sB[r][qd * 4 + 3] = b.w * c;
    }
    __syncthreads();

    int tn = tid & 15, tk = tid >> 4;
    float bb[2][16];
    #pragma unroll
    for (int nn = 0; nn < 2; nn++)
        #pragma unroll
        for (int r = 0; r < 16; r++) bb[nn][r] = sB[r][tn * 2 + nn];

    int qa[2][8];
    #pragma unroll
    for (int nn = 0; nn < 2; nn++) {
        int n = n0 + tn * 2 + nn;
        const int4* qp = (const int4*)(q + (size_t)n * K_TOT + k0 + tk * 8);
        int4 u0 = qp[0], u1 = qp[1];
        qa[nn][0] = u0.x; qa[nn][1] = u0.y; qa[nn][2] = u0.z; qa[nn][3] = u0.w;
        qa[nn][4] = u1.x; qa[nn][5] = u1.y; qa[nn][6] = u1.z; qa[nn][7] = u1.w;
    }

    __half2 owt[2][4];
    float wprev[2];
    #pragma unroll
    for (int kk = 0; kk < 8; kk++) {
        const float4* ap = (const float4*)&sA[tk * 8 + kk][0];
        float4 a0 = ap[0], a1 = ap[1], a2 = ap[2], a3 = ap[3];
        float av[16] = {a0.x, a0.y, a0.z, a0.w, a1.x, a1.y, a1.z, a1.w,
                        a2.x, a2.y, a2.z, a2.w, a3.x, a3.y, a3.z, a3.w};
        #pragma unroll
        for (int nn = 0; nn < 2; nn++) {
            float s0 = 0.f, s1 = 0.f;
            #pragma unroll
            for (int r = 0; r < 16; r += 2) {
                s0 = fmaf(av[r], bb[nn][r], s0);
                s1 = fmaf(av[r + 1], bb[nn][r + 1], s1);
            }
            float w = (float)qa[nn][kk] + (s0 + s1);
            if (kk & 1) owt[nn][kk >> 1] = __floats2half2_rn(wprev[nn], w);
            else        wprev[nn] = w;
        }
    }
    #pragma unroll
    for (int nn = 0; nn < 2; nn++) {
        int n = n0 + tn * 2 + nn;
        uint4 u;
        memcpy(&u, owt[nn], 16);
        *(uint4*)(g_wb + (size_t)n * K2 + k0 + tk * 8) = u;
    }
}

// ---------------------------------------------------------------------------
// Kernel 3: fp16 mma.sync GEMM, 128x128x64 tiles, TMA 3-stage pipeline.
//   R10 structure + (a) per-warp EMPTY arrival (count 8, lane0 arrives),
//   (b) prologue TMA issued before bias staging.
// ---------------------------------------------------------------------------
__global__ void __launch_bounds__(GEMM_THREADS, 2) qlora_gemm_kernel(
    const __grid_constant__ CUtensorMap tmA,
    const __grid_constant__ CUtensorMap tmB,
    const float* __restrict__ scales,
    const float* __restrict__ bias,
    float* __restrict__ out)
{
    extern __shared__ __align__(1024) char smem[];
    uint32_t sb = smem_u32(smem);
    const uint32_t FULLB  = sb + OFF_FULL;
    const uint32_t EMPTYB = sb + OFF_EMPTY;
    float* sbias = (float*)(smem + OFF_BIAS);
    const uint32_t SA0 = sb + OFF_TILES;
    const uint32_t SB0 = SA0 + STAGES * TILE_BYTES;

    int tid = threadIdx.x, wid = tid >> 5, lane = tid & 31;
    int mwarp = wid >> 2, nwarp = wid & 3;

    int mt = blockIdx.x & 63;
    int nt = blockIdx.x >> 6;
    int m0 = mt * 128, n0 = nt * 128;

    if (tid == 0) {
        #pragma unroll
        for (int s = 0; s < STAGES; s++) {
            mbar_init(FULLB + 8 * s, 1);
            mbar_init(EMPTYB + 8 * s, 8);      // one arrive per warp
        }
        asm volatile("fence.proxy.async.shared::cta;" ::: "memory");
    }
    __syncthreads();

    // Prologue TMA first (earliest possible load start)
    if (tid == 0) {
        #pragma unroll
        for (int c = 0; c < STAGES - 1; c++) {
            mbar_expect_tx(FULLB + 8 * c, 2 * TILE_BYTES);
            tma_2d(SA0 + c * TILE_BYTES, &tmA, c * 64, m0, FULLB + 8 * c);
            tma_2d(SB0 + c * TILE_BYTES, &tmB, c * 64, n0, FULLB + 8 * c);
        }
    }
    if (tid < 128) sbias[tid] = bias[n0 + tid];
    __syncthreads();

    uint32_t aRowOff[4], aSw[4];
    {
        int ar = lane & 15;
        #pragma unroll
        for (int i = 0; i < 4; i++) {
            int row = mwarp * 64 + i * 16 + ar;
            aRowOff[i] = row * 128;
            aSw[i] = row & 7;
        }
    }
    uint32_t a_dc = lane >> 4;
    uint32_t bRowOff[2], bSw[2];
    {
        #pragma unroll
        for (int jj = 0; jj < 2; jj++) {
            int row = nwarp * 32 + jj * 16 + ((lane >> 4) << 3) + (lane & 7);
            bRowOff[jj] = row * 128;
            bSw[jj] = row & 7;
        }
    }
    uint32_t b_dc = (lane >> 3) & 1;

    float acc[4][4][4];
    #pragma unroll
    for (int i = 0; i < 4; i++)
        #pragma unroll
        for (int j = 0; j < 4; j++)
            #pragma unroll
            for (int d = 0; d < 4; d++) acc[i][j][d] = 0.f;

    for (int c = 0; c < NCHUNK; c++) {
        if (tid == 0) {
            int n = c + STAGES - 1;
            if (n < NCHUNK) {
                int s = n % STAGES, r = n / STAGES;
                mbar_wait(EMPTYB + 8 * s, (r + 1) & 1);   // fresh stages pass (parity 1)
                mbar_expect_tx(FULLB + 8 * s, 2 * TILE_BYTES);
                tma_2d(SA0 + s * TILE_BYTES, &tmA, n * 64, m0, FULLB + 8 * s);
                tma_2d(SB0 + s * TILE_BYTES, &tmB, n * 64, n0, FULLB + 8 * s);
            }
        }
        int s = c % STAGES, r = c / STAGES;
        mbar_wait(FULLB + 8 * s, r & 1);
        uint32_t sA = SA0 + s * TILE_BYTES;
        uint32_t sBw = SB0 + s * TILE_BYTES;

        #pragma unroll
        for (int ks = 0; ks < 4; ks++) {
            uint32_t cc = 2 * ks;
            uint32_t bfr[8];
            ldsm4(bfr[0], bfr[1], bfr[2], bfr[3],
                  sBw + bRowOff[0] + (((cc + b_dc) ^ bSw[0]) << 4));
            ldsm4(bfr[4], bfr[5], bfr[6], bfr[7],
                  sBw + bRowOff[1] + (((cc + b_dc) ^ bSw[1]) << 4));
            #pragma unroll
            for (int i = 0; i < 4; i++) {
                uint32_t a0, a1, a2, a3;
                ldsm4(a0, a1, a2, a3,
                      sA + aRowOff[i] + (((cc + a_dc) ^ aSw[i]) << 4));
                #pragma unroll
                for (int j = 0; j < 4; j++)
                    mma16816(acc[i][j][0], acc[i][j][1], acc[i][j][2], acc[i][j][3],
                             a0, a1, a2, a3, bfr[2 * j], bfr[2 * j + 1]);
            }
        }
        if (lane == 0) mbar_arrive(EMPTYB + 8 * s);
    }

    float scl = __ldg(scales);
    int g = lane >> 2, tig = lane & 3;
    #pragma unroll
    for (int i = 0; i < 4; i++) {
        int row = m0 + mwarp * 64 + i * 16 + g;
        #pragma unroll
        for (int j = 0; j < 4; j++) {
            int lcol = nwarp * 32 + j * 8 + tig * 2;
            float b0 = sbias[lcol], b1 = sbias[lcol + 1];
            float2 v0, v1;
            v0.x = acc[i][j][0] * scl + b0;
            v0.y = acc[i][j][1] * scl + b1;
            v1.x = acc[i][j][2] * scl + b0;
            v1.y = acc[i][j][3] * scl + b1;
            *(float2*)(out + (size_t)row * N_TOT + n0 + lcol) = v0;
            *(float2*)(out + (size_t)(row + 8) * N_TOT + n0 + lcol) = v1;
        }
    }
}

// ---------------------------------------------------------------------------
// Host launch
// ---------------------------------------------------------------------------
typedef CUresult (*PFN_encodeTiled)(
    CUtensorMap*, CUtensorMapDataType, cuuint32_t, void*,
    const cuuint64_t*, const cuuint64_t*, const cuuint32_t*, const cuuint32_t*,
    CUtensorMapInterleave, CUtensorMapSwizzle, CUtensorMapL2promotion,
    CUtensorMapFloatOOBfill);

static PFN_encodeTiled get_encoder() {
    void* fn = nullptr;
    cudaDriverEntryPointQueryResult qres = cudaDriverEntryPointSymbolNotFound;
    if (cudaGetDriverEntryPointByVersion("cuTensorMapEncodeTiled", &fn, 12000,
                                         cudaEnableDefault, &qres) == cudaSuccess &&
        qres == cudaDriverEntryPointSuccess && fn) {
        return (PFN_encodeTiled)fn;
    }
    fn = nullptr;
    qres = cudaDriverEntryPointSymbolNotFound;
    if (cudaGetDriverEntryPoint("cuTensorMapEncodeTiled", &fn,
                                cudaEnableDefault, &qres) == cudaSuccess &&
        qres == cudaDriverEntryPointSuccess && fn) {
        return (PFN_encodeTiled)fn;
    }
    return nullptr;
}

extern "C" void kernel_launch(void* const* d_in, const int* in_sizes, int n_in,
                              void* d_out, int out_size) {
    const float* x      = (const float*)d_in[0];
    const int*   qw     = (const int*)d_in[1];
    const float* scales = (const float*)d_in[2];
    const float* bias   = (const float*)d_in[3];
    const float* lA     = (const float*)d_in[4];
    const float* lB     = (const float*)d_in[5];
    float* out = (float*)d_out;

    void* p_xh = nullptr;
    void* p_wb = nullptr;
    cudaGetSymbolAddress(&p_xh, g_xh);
    cudaGetSymbolAddress(&p_wb, g_wb);

    static PFN_encodeTiled enc = nullptr;
    if (!enc) enc = get_encoder();
    if (!enc || !p_xh || !p_wb) return;

    CUtensorMap tmA, tmB;
    {
        cuuint64_t dims[2]    = {(cuuint64_t)K2, (cuuint64_t)M_TOT};
        cuuint64_t strides[1] = {(cuuint64_t)K2 * 2};
        cuuint32_t box[2]     = {64, 128};
        cuuint32_t es[2]      = {1, 1};
        if (enc(&tmA, CU_TENSOR_MAP_DATA_TYPE_FLOAT16, 2, p_xh, dims, strides, box, es,
                CU_TENSOR_MAP_INTERLEAVE_NONE, CU_TENSOR_MAP_SWIZZLE_128B,
                CU_TENSOR_MAP_L2_PROMOTION_L2_128B,
                CU_TENSOR_MAP_FLOAT_OOB_FILL_NONE) != CUDA_SUCCESS) return;
    }
    {
        cuuint64_t dims[2]    = {(cuuint64_t)K2, (cuuint64_t)N_TOT};
        cuuint64_t strides[1] = {(cuuint64_t)K2 * 2};
        cuuint32_t box[2]     = {64, 128};
        cuuint32_t es[2]      = {1, 1};
        if (enc(&tmB, CU_TENSOR_MAP_DATA_TYPE_FLOAT16, 2, p_wb, dims, strides, box, es,
                CU_TENSOR_MAP_INTERLEAVE_NONE, CU_TENSOR_MAP_SWIZZLE_128B,
                CU_TENSOR_MAP_L2_PROMOTION_L2_128B,
                CU_TENSOR_MAP_FLOAT_OOB_FILL_NONE) != CUDA_SUCCESS) return;
    }

    // 1) x -> fp16 (pure stream)
    conv_x_kernel<<<(unsigned)((size_t)M_TOT * K_TOT / 8 / 256), 256>>>(x);
    // 2) W_eff = q + (1/scale) * (A@B)^T -> fp16
    {
        dim3 g2(K_TOT / PW_TK, N_TOT / PW_TN);
        prep_w_kernel<<<g2, 256>>>(qw, lA, lB, scales);
    }
    // 3) main GEMM
    cudaFuncSetAttribute(qlora_gemm_kernel,
                         cudaFuncAttributeMaxDynamicSharedMemorySize, SMEM_TOTAL);
    qlora_gemm_kernel<<<(M_TOT / 128) * (N_TOT / 128), GEMM_THREADS, SMEM_TOTAL>>>(
        tmA, tmB, scales, bias, out);
}

// round 16
// speedup vs baseline: 1.0964x; 1.0455x over previous
#include <cuda_runtime.h>
#include <cuda.h>
#include <cuda_fp16.h>
#include <cstdint>
#include <cstddef>
#include <cstring>

// ---------------------------------------------------------------------------
// Problem constants
// ---------------------------------------------------------------------------
#define M_TOT 8192        // B*S
#define N_TOT 4096        // D_OUT
#define K_TOT 4096        // D_IN
#define RANK  16
#define K2    4096
#define NCHUNK 64         // K2 / 64
#define STAGES 4
#define GEMM_THREADS 256

// GEMM tile: 256(M) x 128(N); 8 warps of 64x64
#define TM 256
#define TN 128
#define A_TILE_BYTES 32768    // 256 rows x 128B
#define B_TILE_BYTES 16384    // 128 rows x 128B

// smem layout (bytes, relative to dynamic smem base; base is 1024-aligned)
#define OFF_FULL   0      // 4 x 8B
#define OFF_EMPTY  64     // 4 x 8B
#define OFF_BIAS   128    // 128 floats
#define OFF_TILES  1024
#define SMEM_TOTAL (OFF_TILES + STAGES * (A_TILE_BYTES + B_TILE_BYTES))  // 197632

// prep_w tiling
#define PW_TK 128
#define PW_TN 32

// ---------------------------------------------------------------------------
// Device scratch (allocation-free rule: __device__ globals)
// ---------------------------------------------------------------------------
__device__ __half g_xh[(size_t)M_TOT * K2];   // [8192, 4096] fp16  64 MB
__device__ __half g_wb[(size_t)N_TOT * K2];   // [4096, 4096] fp16  32 MB

// ---------------------------------------------------------------------------
// PTX helpers
// ---------------------------------------------------------------------------
__device__ __forceinline__ uint32_t smem_u32(const void* p) {
    uint32_t a;
    asm("{ .reg .u64 t; cvta.to.shared.u64 t, %1; cvt.u32.u64 %0, t; }"
        : "=r"(a) : "l"(p));
    return a;
}
__device__ __forceinline__ void mbar_init(uint32_t a, uint32_t n) {
    asm volatile("mbarrier.init.shared.b64 [%0], %1;" :: "r"(a), "r"(n) : "memory");
}
__device__ __forceinline__ void mbar_expect_tx(uint32_t a, uint32_t bytes) {
    asm volatile("mbarrier.arrive.expect_tx.shared.b64 _, [%0], %1;"
                 :: "r"(a), "r"(bytes) : "memory");
}
__device__ __forceinline__ void mbar_arrive(uint32_t a) {
    asm volatile("mbarrier.arrive.shared.b64 _, [%0];" :: "r"(a) : "memory");
}
__device__ __forceinline__ void mbar_wait(uint32_t a, uint32_t parity) {
    asm volatile(
        "{\n\t.reg .pred P;\n"
        "W_%=:\n\t"
        "mbarrier.try_wait.parity.acquire.cta.shared::cta.b64 P, [%0], %1, 0x989680;\n\t"
        "@P bra D_%=;\n\t"
        "bra W_%=;\n"
        "D_%=:\n\t}"
        :: "r"(a), "r"(parity) : "memory");
}
__device__ __forceinline__ void tma_2d(uint32_t dst, const CUtensorMap* tm,
                                       int cx, int cy, uint32_t mbar) {
    asm volatile(
        "cp.async.bulk.tensor.2d.shared::cta.global.tile.mbarrier::complete_tx::bytes "
        "[%0], [%1, {%2, %3}], [%4];"
        :: "r"(dst), "l"(tm), "r"(cx), "r"(cy), "r"(mbar) : "memory");
}
__device__ __forceinline__ void ldsm4(uint32_t& r0, uint32_t& r1, uint32_t& r2,
                                      uint32_t& r3, uint32_t addr) {
    asm volatile("ldmatrix.sync.aligned.m8n8.x4.shared.b16 {%0,%1,%2,%3}, [%4];"
                 : "=r"(r0), "=r"(r1), "=r"(r2), "=r"(r3) : "r"(addr));
}
__device__ __forceinline__ void mma16816(float& d0, float& d1, float& d2, float& d3,
                                         uint32_t a0, uint32_t a1, uint32_t a2, uint32_t a3,
                                         uint32_t b0, uint32_t b1) {
    asm volatile(
        "mma.sync.aligned.m16n8k16.row.col.f32.f16.f16.f32 "
        "{%0,%1,%2,%3}, {%4,%5,%6,%7}, {%8,%9}, {%0,%1,%2,%3};"
        : "+f"(d0), "+f"(d1), "+f"(d2), "+f"(d3)
        : "r"(a0), "r"(a1), "r"(a2), "r"(a3), "r"(b0), "r"(b1));
}

// ---------------------------------------------------------------------------
// Kernel 1: pure stream convert  g_xh = fp16(x).  8 elements / thread.
// ---------------------------------------------------------------------------
__global__ void __launch_bounds__(256) conv_x_kernel(const float* __restrict__ x) {
    size_t i = ((size_t)blockIdx.x * 256 + threadIdx.x) * 8;
    float4 v0 = *(const float4*)(x + i);
    float4 v1 = *(const float4*)(x + i + 4);
    __half2 h[4];
    h[0] = __floats2half2_rn(v0.x, v0.y);
    h[1] = __floats2half2_rn(v0.z, v0.w);
    h[2] = __floats2half2_rn(v1.x, v1.y);
    h[3] = __floats2half2_rn(v1.z, v1.w);
    uint4 u;
    memcpy(&u, h, 16);
    *(uint4*)(g_xh + i) = u;
}

// ---------------------------------------------------------------------------
// Kernel 2: W_eff[n][k] = fp16( q[n][k] + (1/scale) * sum_r A[k][r]*B[r][n] )
// ---------------------------------------------------------------------------
__global__ void __launch_bounds__(256) prep_w_kernel(const int* __restrict__ q,
                                                     const float* __restrict__ lA,
                                                     const float* __restrict__ lB,
                                                     const float* __restrict__ scales) {
    __shared__ float sA[PW_TK][16];
    __shared__ float sB[16][PW_TN];
    int tid = threadIdx.x;
    int k0 = blockIdx.x * PW_TK, n0 = blockIdx.y * PW_TN;
    float c = 1.0f / __ldg(scales);

    #pragma unroll
    for (int it = 0; it < 2; it++) {
        int idx = tid + it * 256;
        int k = idx >> 2, qd = idx & 3;
        float4 a = ((const float4*)(lA + (size_t)(k0 + k) * RANK))[qd];
        sA[k][qd * 4 + 0] = a.x;
        sA[k][qd * 4 + 1] = a.y;
        sA[k][qd * 4 + 2] = a.z;
        sA[k][qd * 4 + 3] = a.w;
    }
    if (tid < 128) {
        int r = tid >> 3, qd = tid & 7;
        float4 b = ((const float4*)(lB + (size_t)r * N_TOT + n0))[qd];
        sB[r][qd * 4 + 0] = b.x * c;
        sB[r][qd * 4 + 1] = b.y * c;
        sB[r][qd * 4 + 2] = b.z * c;
        sB[r][qd * 4 + 3] = b.w * c;
    }
    __syncthreads();

    int tn = tid & 15, tk = tid >> 4;
    float bb[2][16];
    #pragma unroll
    for (int nn = 0; nn < 2; nn++)
        #pragma unroll
        for (int r = 0; r < 16; r++) bb[nn][r] = sB[r][tn * 2 + nn];

    int qa[2][8];
    #pragma unroll
    for (int nn = 0; nn < 2; nn++) {
        int n = n0 + tn * 2 + nn;
        const int4* qp = (const int4*)(q + (size_t)n * K_TOT + k0 + tk * 8);
        int4 u0 = qp[0], u1 = qp[1];
        qa[nn][0] = u0.x; qa[nn][1] = u0.y; qa[nn][2] = u0.z; qa[nn][3] = u0.w;
        qa[nn][4] = u1.x; qa[nn][5] = u1.y; qa[nn][6] = u1.z; qa[nn][7] = u1.w;
    }

    __half2 owt[2][4];
    float wprev[2];
    #pragma unroll
    for (int kk = 0; kk < 8; kk++) {
        const float4* ap = (const float4*)&sA[tk * 8 + kk][0];
        float4 a0 = ap[0], a1 = ap[1], a2 = ap[2], a3 = ap[3];
        float av[16] = {a0.x, a0.y, a0.z, a0.w, a1.x, a1.y, a1.z, a1.w,
                        a2.x, a2.y, a2.z, a2.w, a3.x, a3.y, a3.z, a3.w};
        #pragma unroll
        for (int nn = 0; nn < 2; nn++) {
            float s0 = 0.f, s1 = 0.f;
            #pragma unroll
            for (int r = 0; r < 16; r += 2) {
                s0 = fmaf(av[r], bb[nn][r], s0);
                s1 = fmaf(av[r + 1], bb[nn][r + 1], s1);
            }
            float w = (float)qa[nn][kk] + (s0 + s1);
            if (kk & 1) owt[nn][kk >> 1] = __floats2half2_rn(wprev[nn], w);
            else        wprev[nn] = w;
        }
    }
    #pragma unroll
    for (int nn = 0; nn < 2; nn++) {
        int n = n0 + tn * 2 + nn;
        uint4 u;
        memcpy(&u, owt[nn], 16);
        *(uint4*)(g_wb + (size_t)n * K2 + k0 + tk * 8) = u;
    }
}

// ---------------------------------------------------------------------------
// Kernel 3: fp16 mma.sync GEMM, 256x128 CTA tile, 8 warps of 64x64,
//   4-stage TMA pipeline, 1 CTA/SM.
// ---------------------------------------------------------------------------
__global__ void __launch_bounds__(GEMM_THREADS, 1) qlora_gemm_kernel(
    const __grid_constant__ CUtensorMap tmA,
    const __grid_constant__ CUtensorMap tmB,
    const float* __restrict__ scales,
    const float* __restrict__ bias,
    float* __restrict__ out)
{
    extern __shared__ __align__(1024) char smem[];
    uint32_t sb = smem_u32(smem);
    const uint32_t FULLB  = sb + OFF_FULL;
    const uint32_t EMPTYB = sb + OFF_EMPTY;
    float* sbias = (float*)(smem + OFF_BIAS);
    const uint32_t SA0 = sb + OFF_TILES;                          // 4 x 32KB
    const uint32_t SB0 = SA0 + STAGES * A_TILE_BYTES;             // 4 x 16KB

    int tid = threadIdx.x, wid = tid >> 5, lane = tid & 31;
    int mwarp = wid >> 1, nwarp = wid & 1;   // 4(m) x 2(n) warps, 64x64 each

    int mt = blockIdx.x & 31;                // 32 m-tiles of 256
    int nt = blockIdx.x >> 5;                // 32 n-tiles of 128
    int m0 = mt * TM, n0 = nt * TN;

    if (tid == 0) {
        #pragma unroll
        for (int s = 0; s < STAGES; s++) {
            mbar_init(FULLB + 8 * s, 1);
            mbar_init(EMPTYB + 8 * s, 8);    // one arrive per warp
        }
        asm volatile("fence.proxy.async.shared::cta;" ::: "memory");
    }
    __syncthreads();

    // Prologue: issue chunks 0..STAGES-2
    if (tid == 0) {
        #pragma unroll
        for (int c = 0; c < STAGES - 1; c++) {
            mbar_expect_tx(FULLB + 8 * c, A_TILE_BYTES + B_TILE_BYTES);
            tma_2d(SA0 + c * A_TILE_BYTES, &tmA, c * 64, m0, FULLB + 8 * c);
            tma_2d(SB0 + c * B_TILE_BYTES, &tmB, c * 64, n0, FULLB + 8 * c);
        }
    }
    if (tid < 128) sbias[tid] = bias[n0 + tid];
    __syncthreads();

    // ldmatrix address components (SW128: phys16B = c ^ (row&7))
    uint32_t aRowOff[4], aSw[4];
    {
        int ar = lane & 15;
        #pragma unroll
        for (int i = 0; i < 4; i++) {
            int row = mwarp * 64 + i * 16 + ar;
            aRowOff[i] = row * 128;
            aSw[i] = row & 7;
        }
    }
    uint32_t a_dc = lane >> 4;
    uint32_t bRowOff[4], bSw[4];
    {
        #pragma unroll
        for (int jj = 0; jj < 4; jj++) {
            int row = nwarp * 64 + jj * 16 + ((lane >> 4) << 3) + (lane & 7);
            bRowOff[jj] = row * 128;
            bSw[jj] = row & 7;
        }
    }
    uint32_t b_dc = (lane >> 3) & 1;

    float acc[4][8][4];
    #pragma unroll
    for (int i = 0; i < 4; i++)
        #pragma unroll
        for (int j = 0; j < 8; j++)
            #pragma unroll
            for (int d = 0; d < 4; d++) acc[i][j][d] = 0.f;

    for (int c = 0; c < NCHUNK; c++) {
        if (tid == 0) {
            int n = c + STAGES - 1;
            if (n < NCHUNK) {
                int s = n & (STAGES - 1), r = n >> 2;
                mbar_wait(EMPTYB + 8 * s, (r + 1) & 1);   // fresh stages pass (parity 1)
                mbar_expect_tx(FULLB + 8 * s, A_TILE_BYTES + B_TILE_BYTES);
                tma_2d(SA0 + s * A_TILE_BYTES, &tmA, n * 64, m0, FULLB + 8 * s);
                tma_2d(SB0 + s * B_TILE_BYTES, &tmB, n * 64, n0, FULLB + 8 * s);
            }
        }
        int s = c & (STAGES - 1), r = c >> 2;
        mbar_wait(FULLB + 8 * s, r & 1);
        uint32_t sA = SA0 + s * A_TILE_BYTES;
        uint32_t sBw = SB0 + s * B_TILE_BYTES;

        #pragma unroll
        for (int ks = 0; ks < 4; ks++) {
            uint32_t cc = 2 * ks;
            uint32_t bfr[16];
            #pragma unroll
            for (int jj = 0; jj < 4; jj++)
                ldsm4(bfr[4 * jj], bfr[4 * jj + 1], bfr[4 * jj + 2], bfr[4 * jj + 3],
                      sBw + bRowOff[jj] + (((cc + b_dc) ^ bSw[jj]) << 4));
            #pragma unroll
            for (int i = 0; i < 4; i++) {
                uint32_t a0, a1, a2, a3;
                ldsm4(a0, a1, a2, a3,
                      sA + aRowOff[i] + (((cc + a_dc) ^ aSw[i]) << 4));
                #pragma unroll
                for (int j = 0; j < 8; j++)
                    mma16816(acc[i][j][0], acc[i][j][1], acc[i][j][2], acc[i][j][3],
                             a0, a1, a2, a3, bfr[2 * j], bfr[2 * j + 1]);
            }
        }
        if (lane == 0) mbar_arrive(EMPTYB + 8 * s);
    }

    // Epilogue: out = scale*acc + bias
    float scl = __ldg(scales);
    int g = lane >> 2, tig = lane & 3;
    #pragma unroll
    for (int i = 0; i < 4; i++) {
        int row = m0 + mwarp * 64 + i * 16 + g;
        #pragma unroll
        for (int j = 0; j < 8; j++) {
            int lcol = nwarp * 64 + j * 8 + tig * 2;
            float b0 = sbias[lcol], b1 = sbias[lcol + 1];
            float2 v0, v1;
            v0.x = acc[i][j][0] * scl + b0;
            v0.y = acc[i][j][1] * scl + b1;
            v1.x = acc[i][j][2] * scl + b0;
            v1.y = acc[i][j][3] * scl + b1;
            *(float2*)(out + (size_t)row * N_TOT + n0 + lcol) = v0;
            *(float2*)(out + (size_t)(row + 8) * N_TOT + n0 + lcol) = v1;
        }
    }
}

// ---------------------------------------------------------------------------
// Host launch
// ---------------------------------------------------------------------------
typedef CUresult (*PFN_encodeTiled)(
    CUtensorMap*, CUtensorMapDataType, cuuint32_t, void*,
    const cuuint64_t*, const cuuint64_t*, const cuuint32_t*, const cuuint32_t*,
    CUtensorMapInterleave, CUtensorMapSwizzle, CUtensorMapL2promotion,
    CUtensorMapFloatOOBfill);

static PFN_encodeTiled get_encoder() {
    void* fn = nullptr;
    cudaDriverEntryPointQueryResult qres = cudaDriverEntryPointSymbolNotFound;
    if (cudaGetDriverEntryPointByVersion("cuTensorMapEncodeTiled", &fn, 12000,
                                         cudaEnableDefault, &qres) == cudaSuccess &&
        qres == cudaDriverEntryPointSuccess && fn) {
        return (PFN_encodeTiled)fn;
    }
    fn = nullptr;
    qres = cudaDriverEntryPointSymbolNotFound;
    if (cudaGetDriverEntryPoint("cuTensorMapEncodeTiled", &fn,
                                cudaEnableDefault, &qres) == cudaSuccess &&
        qres == cudaDriverEntryPointSuccess && fn) {
        return (PFN_encodeTiled)fn;
    }
    return nullptr;
}

extern "C" void kernel_launch(void* const* d_in, const int* in_sizes, int n_in,
                              void* d_out, int out_size) {
    const float* x      = (const float*)d_in[0];
    const int*   qw     = (const int*)d_in[1];
    const float* scales = (const float*)d_in[2];
    const float* bias   = (const float*)d_in[3];
    const float* lA     = (const float*)d_in[4];
    const float* lB     = (const float*)d_in[5];
    float* out = (float*)d_out;

    void* p_xh = nullptr;
    void* p_wb = nullptr;
    cudaGetSymbolAddress(&p_xh, g_xh);
    cudaGetSymbolAddress(&p_wb, g_wb);

    static PFN_encodeTiled enc = nullptr;
    if (!enc) enc = get_encoder();
    if (!enc || !p_xh || !p_wb) return;

    CUtensorMap tmA, tmB;
    {
        cuuint64_t dims[2]    = {(cuuint64_t)K2, (cuuint64_t)M_TOT};
        cuuint64_t strides[1] = {(cuuint64_t)K2 * 2};
        cuuint32_t box[2]     = {64, 256};       // 256-row A tile
        cuuint32_t es[2]      = {1, 1};
        if (enc(&tmA, CU_TENSOR_MAP_DATA_TYPE_FLOAT16, 2, p_xh, dims, strides, box, es,
                CU_TENSOR_MAP_INTERLEAVE_NONE, CU_TENSOR_MAP_SWIZZLE_128B,
                CU_TENSOR_MAP_L2_PROMOTION_L2_128B,
                CU_TENSOR_MAP_FLOAT_OOB_FILL_NONE) != CUDA_SUCCESS) return;
    }
    {
        cuuint64_t dims[2]    = {(cuuint64_t)K2, (cuuint64_t)N_TOT};
        cuuint64_t strides[1] = {(cuuint64_t)K2 * 2};
        cuuint32_t box[2]     = {64, 128};
        cuuint32_t es[2]      = {1, 1};
        if (enc(&tmB, CU_TENSOR_MAP_DATA_TYPE_FLOAT16, 2, p_wb, dims, strides, box, es,
                CU_TENSOR_MAP_INTERLEAVE_NONE, CU_TENSOR_MAP_SWIZZLE_128B,
                CU_TENSOR_MAP_L2_PROMOTION_L2_128B,
                CU_TENSOR_MAP_FLOAT_OOB_FILL_NONE) != CUDA_SUCCESS) return;
    }

    // 1) x -> fp16 (pure stream)
    conv_x_kernel<<<(unsigned)((size_t)M_TOT * K_TOT / 8 / 256), 256>>>(x);
    // 2) W_eff = q + (1/scale) * (A@B)^T -> fp16
    {
        dim3 g2(K_TOT / PW_TK, N_TOT / PW_TN);
        prep_w_kernel<<<g2, 256>>>(qw, lA, lB, scales);
    }
    // 3) main GEMM (256x128 tiles)
    cudaFuncSetAttribute(qlora_gemm_kernel,
                         cudaFuncAttributeMaxDynamicSharedMemorySize, SMEM_TOTAL);
    qlora_gemm_kernel<<<(M_TOT / TM) * (N_TOT / TN), GEMM_THREADS, SMEM_TOTAL>>>(
        tmA, tmB, scales, bias, out);
}